// round 1
// baseline (speedup 1.0000x reference)
#include <cuda_runtime.h>
#include <cstdint>
#include <cstddef>

#define NN 100000
#define NE 600000
#define H 128
#define FIN 39

#define BM 64
#define BN 128
#define BK 32
#define PADA 4

// ---------------- scratch (device globals; no allocation allowed) ----------------
__device__ float g_h[(size_t)NN * H];        // node features          [N,128]
__device__ float g_PQ[(size_t)NN * 4 * H];   // P_a|Q_a|P_e|Q_e        [N,512]
__device__ float g_S[(size_t)NN * 2 * H];    // S_ally | S_enc         [N,256]
__device__ float g_deg[2 * NN];              // deg_ally, deg_enc (as float)

// ---------------- utility kernels ----------------
__global__ void fill_zero(float4* __restrict__ p, int n4) {
    int i = blockIdx.x * blockDim.x + threadIdx.x;
    int stride = gridDim.x * blockDim.x;
    float4 z = make_float4(0.f, 0.f, 0.f, 0.f);
    for (; i < n4; i += stride) p[i] = z;
}

__global__ void deg_kernel(const int* __restrict__ eia, const int* __restrict__ eie,
                           float* __restrict__ deg) {
    int t = blockIdx.x * blockDim.x + threadIdx.x;
    if (t < NE) {
        atomicAdd(&deg[eia[NE + t]], 1.f);
    } else if (t < 2 * NE) {
        atomicAdd(&deg[NN + eie[NE + (t - NE)]], 1.f);
    }
}

// ---------------- input projection: h = relu(x @ W_in + b_in) ----------------
#define IPN 16
__global__ void __launch_bounds__(128) input_proj(const float* __restrict__ x,
                                                  const float* __restrict__ Win,
                                                  const float* __restrict__ bin,
                                                  float* __restrict__ h) {
    __shared__ float Ws[FIN * H];
    __shared__ float xs[IPN][FIN + 1];
    int tid = threadIdx.x;
    for (int i = tid; i < FIN * H; i += 128) Ws[i] = Win[i];
    int n0 = blockIdx.x * IPN;  // N divisible by 16
    for (int i = tid; i < IPN * FIN; i += 128) {
        int r = i / FIN, c = i - r * FIN;
        xs[r][c] = x[(size_t)(n0 + r) * FIN + c];
    }
    __syncthreads();
    float acc[IPN];
    float bv = bin[tid];
#pragma unroll
    for (int r = 0; r < IPN; r++) acc[r] = bv;
    for (int k = 0; k < FIN; k++) {
        float wv = Ws[k * H + tid];
#pragma unroll
        for (int r = 0; r < IPN; r++) acc[r] = fmaf(xs[r][k], wv, acc[r]);
    }
#pragma unroll
    for (int r = 0; r < IPN; r++)
        h[(size_t)(n0 + r) * H + tid] = fmaxf(acc[r], 0.f);
}

// ---------------- edge phase: S[tgt] += relu(P[tgt] + Q[src] + ea @ W1c) ----------------
__global__ void __launch_bounds__(256) edge_kernel(const int* __restrict__ ei,
                                                   const float* __restrict__ ea,
                                                   const float* __restrict__ PQ, int pq_off,
                                                   const float* __restrict__ w1c,
                                                   float* __restrict__ S, int s_off) {
    __shared__ __align__(16) float w[2 * H];
    if (threadIdx.x < 2 * H) w[threadIdx.x] = w1c[threadIdx.x];
    __syncthreads();
    int e = (blockIdx.x * 256 + threadIdx.x) >> 5;  // warp per edge; grid sized exactly
    int lane = threadIdx.x & 31;
    if (e >= NE) return;
    int src = ei[e];
    int tgt = ei[NE + e];
    float e0 = ea[2 * e], e1 = ea[2 * e + 1];
    float4 p = *(const float4*)&PQ[(size_t)tgt * 512 + pq_off + lane * 4];
    float4 q = *(const float4*)&PQ[(size_t)src * 512 + pq_off + 128 + lane * 4];
    float4 w0 = *(const float4*)&w[lane * 4];
    float4 w1 = *(const float4*)&w[H + lane * 4];
    float4 t;
    t.x = fmaxf(fmaf(e0, w0.x, fmaf(e1, w1.x, p.x + q.x)), 0.f);
    t.y = fmaxf(fmaf(e0, w0.y, fmaf(e1, w1.y, p.y + q.y)), 0.f);
    t.z = fmaxf(fmaf(e0, w0.z, fmaf(e1, w1.z, p.z + q.z)), 0.f);
    t.w = fmaxf(fmaf(e0, w0.w, fmaf(e1, w1.w, p.w + q.w)), 0.f);
    float* dst = &S[(size_t)tgt * 256 + s_off + lane * 4];
    asm volatile("red.global.add.v4.f32 [%0], {%1,%2,%3,%4};"
                 :: "l"(dst), "f"(t.x), "f"(t.y), "f"(t.z), "f"(t.w) : "memory");
}

// ---------------- tiled SGEMM with fused epilogues ----------------
// MODE 0 (PQ):     out[:, y*128:(y+1)*128] = h @ B[y] (+ bias for y==0,2), ldo=512
// MODE 1 (COMBINE): u = S@[W2a;W2e] + h + dega*b2a + dege*b2e; h = LayerNorm(u)
// MODE 2 (COMB):   out = resid + relu(h @ B0 + bias0)
template <int MODE>
__global__ void __launch_bounds__(256) gemm_kernel(
    const float* __restrict__ A, int lda, int Ktot,
    const float* __restrict__ B0, const float* __restrict__ B1,
    const float* __restrict__ B2, const float* __restrict__ B3,
    const float* __restrict__ bias0, const float* __restrict__ bias2,
    const float* __restrict__ resid,
    const float* __restrict__ dega, const float* __restrict__ dege,
    const float* __restrict__ b2a, const float* __restrict__ b2e,
    const float* __restrict__ lng, const float* __restrict__ lnb,
    float* __restrict__ out, int ldo) {
    // shared: GEMM staging, reused as LN staging in MODE 1
    constexpr int SM_GEMM = BK * (BM + PADA) + BK * BN;   // 6272 floats
    constexpr int SM_LN = BM * (BN + 4);                  // 8448 floats
    constexpr int SMSZ = (MODE == 1) ? (SM_LN > SM_GEMM ? SM_LN : SM_GEMM) : SM_GEMM;
    __shared__ __align__(16) float smem[SMSZ];
    float(*As)[BM + PADA] = (float(*)[BM + PADA])smem;
    float(*Bs)[BN] = (float(*)[BN])(smem + BK * (BM + PADA));

    int tid = threadIdx.x;
    int tx = tid & 15;   // col group (8 cols)
    int ty = tid >> 4;   // row group (4 rows)
    int row0 = blockIdx.x * BM;

    const float* B = B0;
    const float* bias = bias0;
    int ocol = 0;
    if (MODE == 0) {
        int y = blockIdx.y;
        B = (y == 0) ? B0 : (y == 1) ? B1 : (y == 2) ? B2 : B3;
        bias = (y == 0) ? bias0 : (y == 2) ? bias2 : nullptr;
        ocol = y * BN;
    }

    float acc[4][8];
#pragma unroll
    for (int r = 0; r < 4; r++)
#pragma unroll
        for (int c = 0; c < 8; c++) acc[r][c] = 0.f;

    for (int kb = 0; kb < Ktot; kb += BK) {
        const float* Bp = B;
        int kk = kb;
        if (MODE == 1 && kb >= H) { Bp = B1; kk = kb - H; }
        // stage A (transposed): 64 rows x 32 k
        int ka = tid & 31, ra0 = tid >> 5;
#pragma unroll
        for (int i = 0; i < 8; i++) {
            int r = ra0 + i * 8;
            int gr = row0 + r;
            As[ka][r] = (gr < NN) ? A[(size_t)gr * lda + kb + ka] : 0.f;
        }
        // stage B: 32 k x 128 cols
        int cb = tid & 127, kb0 = tid >> 7;
#pragma unroll
        for (int i = 0; i < 16; i++) {
            int k = kb0 + i * 2;
            Bs[k][cb] = Bp[(size_t)(kk + k) * H + cb];
        }
        __syncthreads();
#pragma unroll
        for (int k = 0; k < BK; k++) {
            float a[4], b[8];
            *(float4*)a = *(const float4*)&As[k][ty * 4];
            *(float4*)b = *(const float4*)&Bs[k][tx * 8];
            *(float4*)(b + 4) = *(const float4*)&Bs[k][tx * 8 + 4];
#pragma unroll
            for (int r = 0; r < 4; r++)
#pragma unroll
                for (int c = 0; c < 8; c++) acc[r][c] = fmaf(a[r], b[c], acc[r][c]);
        }
        __syncthreads();
    }

    int col0 = tx * 8;
    if (MODE == 0) {
        float bv[8];
#pragma unroll
        for (int c = 0; c < 8; c++) bv[c] = bias ? bias[col0 + c] : 0.f;
#pragma unroll
        for (int r = 0; r < 4; r++) {
            int gr = row0 + ty * 4 + r;
            if (gr < NN) {
                float o[8];
#pragma unroll
                for (int c = 0; c < 8; c++) o[c] = acc[r][c] + bv[c];
                *(float4*)&out[(size_t)gr * ldo + ocol + col0] = *(float4*)o;
                *(float4*)&out[(size_t)gr * ldo + ocol + col0 + 4] = *(float4*)(o + 4);
            }
        }
    } else if (MODE == 2) {
        float bv[8];
#pragma unroll
        for (int c = 0; c < 8; c++) bv[c] = bias0[col0 + c];
#pragma unroll
        for (int r = 0; r < 4; r++) {
            int gr = row0 + ty * 4 + r;
            if (gr < NN) {
                float o[8];
#pragma unroll
                for (int c = 0; c < 8; c++) {
                    float v = fmaxf(acc[r][c] + bv[c], 0.f);
                    o[c] = v + resid[(size_t)gr * H + col0 + c];
                }
                *(float4*)&out[(size_t)gr * ldo + col0] = *(float4*)o;
                *(float4*)&out[(size_t)gr * ldo + col0 + 4] = *(float4*)(o + 4);
            }
        }
    } else {
        // MODE 1: combine residual + deg*b2, then LayerNorm per row
        float(*V)[BN + 4] = (float(*)[BN + 4])smem;
#pragma unroll
        for (int r = 0; r < 4; r++) {
            int rr = ty * 4 + r;
            int gr = row0 + rr;
            float da = 0.f, de = 0.f;
            if (gr < NN) { da = dega[gr]; de = dege[gr]; }
            float o[8];
#pragma unroll
            for (int c = 0; c < 8; c++) {
                int col = col0 + c;
                float v = acc[r][c];
                if (gr < NN)
                    v += resid[(size_t)gr * H + col] + da * b2a[col] + de * b2e[col];
                o[c] = v;
            }
            *(float4*)&V[rr][col0] = *(float4*)o;
            *(float4*)&V[rr][col0 + 4] = *(float4*)(o + 4);
        }
        __syncthreads();
        int warp = tid >> 5, lane = tid & 31;
#pragma unroll
        for (int rr = 0; rr < 8; rr++) {
            int r = warp * 8 + rr;
            int gr = row0 + r;
            float4 v = *(float4*)&V[r][lane * 4];
            float s = v.x + v.y + v.z + v.w;
            float s2 = v.x * v.x + v.y * v.y + v.z * v.z + v.w * v.w;
#pragma unroll
            for (int off = 16; off; off >>= 1) {
                s += __shfl_xor_sync(0xffffffffu, s, off);
                s2 += __shfl_xor_sync(0xffffffffu, s2, off);
            }
            float mu = s * (1.f / 128.f);
            float var = s2 * (1.f / 128.f) - mu * mu;
            float rstd = rsqrtf(var + 1e-5f);
            if (gr < NN) {
                float4 g = *(const float4*)&lng[lane * 4];
                float4 bb = *(const float4*)&lnb[lane * 4];
                float4 o;
                o.x = (v.x - mu) * rstd * g.x + bb.x;
                o.y = (v.y - mu) * rstd * g.y + bb.y;
                o.z = (v.z - mu) * rstd * g.z + bb.z;
                o.w = (v.w - mu) * rstd * g.w + bb.w;
                *(float4*)&out[(size_t)gr * H + lane * 4] = o;
            }
        }
    }
}

// ---------------- launch ----------------
extern "C" void kernel_launch(void* const* d_in, const int* in_sizes, int n_in,
                              void* d_out, int out_size) {
    (void)in_sizes; (void)n_in; (void)out_size;
    const float* x       = (const float*)d_in[0];
    const int*   ally_ei = (const int*)d_in[1];
    const float* ally_ea = (const float*)d_in[2];
    const int*   enc_ei  = (const int*)d_in[3];
    const float* enc_ea  = (const float*)d_in[4];
    const float* W_in    = (const float*)d_in[5];
    const float* b_in    = (const float*)d_in[6];
    const float* ally_W1 = (const float*)d_in[7];
    const float* ally_b1 = (const float*)d_in[8];
    const float* ally_W2 = (const float*)d_in[9];
    const float* ally_b2 = (const float*)d_in[10];
    const float* enc_W1  = (const float*)d_in[11];
    const float* enc_b1  = (const float*)d_in[12];
    const float* enc_W2  = (const float*)d_in[13];
    const float* enc_b2  = (const float*)d_in[14];
    const float* ln_g    = (const float*)d_in[15];
    const float* ln_b    = (const float*)d_in[16];
    const float* comb_W  = (const float*)d_in[17];
    const float* comb_b  = (const float*)d_in[18];
    float* out = (float*)d_out;

    float *h, *PQ, *S, *deg;
    cudaGetSymbolAddress((void**)&h, g_h);
    cudaGetSymbolAddress((void**)&PQ, g_PQ);
    cudaGetSymbolAddress((void**)&S, g_S);
    cudaGetSymbolAddress((void**)&deg, g_deg);
    float* dega = deg;
    float* dege = deg + NN;

    const int nblk = (NN + BM - 1) / BM;  // 1563

    // degree (recomputed every call for determinism)
    fill_zero<<<128, 256>>>((float4*)deg, 2 * NN / 4);
    deg_kernel<<<(2 * NE + 255) / 256, 256>>>(ally_ei, enc_ei, deg);

    // input projection
    input_proj<<<NN / IPN, 128>>>(x, W_in, b_in, h);

    for (int i = 0; i < 2; i++) {
        const float* aW1 = ally_W1 + (size_t)i * 258 * H;
        const float* eW1 = enc_W1 + (size_t)i * 258 * H;

        // zero S
        fill_zero<<<2048, 256>>>((float4*)S, NN * 2 * H / 4);

        // P/Q for both edge types: [N,128] @ four [128,128] weights -> [N,512]
        gemm_kernel<0><<<dim3(nblk, 4), 256>>>(
            h, H, H,
            aW1, aW1 + 128 * H, eW1, eW1 + 128 * H,
            ally_b1 + i * H, enc_b1 + i * H,
            nullptr, nullptr, nullptr, nullptr, nullptr, nullptr, nullptr,
            PQ, 4 * H);

        // edge scatter (warp per edge; E divisible by 8)
        edge_kernel<<<NE / 8, 256>>>(ally_ei, ally_ea, PQ, 0, aW1 + 256 * H, S, 0);
        edge_kernel<<<NE / 8, 256>>>(enc_ei, enc_ea, PQ, 256, eW1 + 256 * H, S, 128);

        // combine: h = LN(h + S_a@W2a + dega*b2a + S_e@W2e + dege*b2e)
        gemm_kernel<1><<<nblk, 256>>>(
            S, 2 * H, 2 * H,
            ally_W2 + (size_t)i * H * H, enc_W2 + (size_t)i * H * H,
            nullptr, nullptr, nullptr, nullptr,
            h, dega, dege,
            ally_b2 + i * H, enc_b2 + i * H,
            ln_g + i * H, ln_b + i * H,
            h, H);

        // comb MLP: h = h + relu(h @ comb_W + comb_b); last layer writes d_out
        float* dst = (i == 1) ? out : h;
        gemm_kernel<2><<<nblk, 256>>>(
            h, H, H,
            comb_W + (size_t)i * H * H, nullptr, nullptr, nullptr,
            comb_b + i * H, nullptr,
            h, nullptr, nullptr, nullptr, nullptr, nullptr, nullptr,
            dst, H);
    }
}

// round 2
// speedup vs baseline: 1.2202x; 1.2202x over previous
#include <cuda_runtime.h>
#include <cstdint>
#include <cstddef>

#define NN 100000
#define NE 600000
#define H 128
#define FIN 39

#define BM 128
#define BN 128
#define BK 32

// ---------------- scratch (device globals; no allocation allowed) ----------------
__device__ float g_h[(size_t)NN * H];        // node features          [N,128]
__device__ float g_PQ[(size_t)NN * 4 * H];   // P_a|Q_a|P_e|Q_e        [N,512]
__device__ float g_S[(size_t)NN * 2 * H];    // S_ally | S_enc         [N,256]
__device__ float g_deg[2 * NN];              // deg_ally, deg_enc (as float)

// ---------------- utility kernels ----------------
__global__ void fill_zero(float4* __restrict__ p, int n4) {
    int i = blockIdx.x * blockDim.x + threadIdx.x;
    int stride = gridDim.x * blockDim.x;
    float4 z = make_float4(0.f, 0.f, 0.f, 0.f);
    for (; i < n4; i += stride) p[i] = z;
}

__global__ void deg_kernel(const int* __restrict__ eia, const int* __restrict__ eie,
                           float* __restrict__ deg) {
    int t = blockIdx.x * blockDim.x + threadIdx.x;
    if (t < NE) {
        atomicAdd(&deg[eia[NE + t]], 1.f);
    } else if (t < 2 * NE) {
        atomicAdd(&deg[NN + eie[NE + (t - NE)]], 1.f);
    }
}

// ---------------- input projection: h = relu(x @ W_in + b_in) ----------------
#define IPN 16
__global__ void __launch_bounds__(128) input_proj(const float* __restrict__ x,
                                                  const float* __restrict__ Win,
                                                  const float* __restrict__ bin,
                                                  float* __restrict__ h) {
    __shared__ float Ws[FIN * H];
    __shared__ float xs[IPN][FIN + 1];
    int tid = threadIdx.x;
    for (int i = tid; i < FIN * H; i += 128) Ws[i] = Win[i];
    int n0 = blockIdx.x * IPN;  // N divisible by 16
    for (int i = tid; i < IPN * FIN; i += 128) {
        int r = i / FIN, c = i - r * FIN;
        xs[r][c] = x[(size_t)(n0 + r) * FIN + c];
    }
    __syncthreads();
    float acc[IPN];
    float bv = bin[tid];
#pragma unroll
    for (int r = 0; r < IPN; r++) acc[r] = bv;
    for (int k = 0; k < FIN; k++) {
        float wv = Ws[k * H + tid];
#pragma unroll
        for (int r = 0; r < IPN; r++) acc[r] = fmaf(xs[r][k], wv, acc[r]);
    }
#pragma unroll
    for (int r = 0; r < IPN; r++)
        h[(size_t)(n0 + r) * H + tid] = fmaxf(acc[r], 0.f);
}

// ---------------- edge phase (both edge sets in one launch) ----------------
// warp per edge: S[tgt] += relu(P[tgt] + Q[src] + ea @ W1c)
__global__ void __launch_bounds__(256) edge_kernel(
    const int* __restrict__ eia, const float* __restrict__ eaa,
    const int* __restrict__ eie, const float* __restrict__ eae,
    const float* __restrict__ PQ,
    const float* __restrict__ w1ca, const float* __restrict__ w1ce,
    float* __restrict__ S) {
    __shared__ __align__(16) float w[512];
    w[threadIdx.x] = w1ca[threadIdx.x];
    w[256 + threadIdx.x] = w1ce[threadIdx.x];
    __syncthreads();
    unsigned gw = blockIdx.x * 8u + (threadIdx.x >> 5);
    int lane = threadIdx.x & 31;
    const int* ei;
    const float* ea;
    int pq_off, s_off, woff, e;
    if (gw < NE) {
        e = gw; ei = eia; ea = eaa; pq_off = 0; s_off = 0; woff = 0;
    } else {
        e = gw - NE; ei = eie; ea = eae; pq_off = 256; s_off = 128; woff = 256;
    }
    int src = ei[e];
    int tgt = ei[NE + e];
    float e0 = ea[2 * e], e1 = ea[2 * e + 1];
    float4 p = *(const float4*)&PQ[(size_t)tgt * 512 + pq_off + lane * 4];
    float4 q = *(const float4*)&PQ[(size_t)src * 512 + pq_off + 128 + lane * 4];
    float4 w0 = *(const float4*)&w[woff + lane * 4];
    float4 w1 = *(const float4*)&w[woff + H + lane * 4];
    float4 t;
    t.x = fmaxf(fmaf(e0, w0.x, fmaf(e1, w1.x, p.x + q.x)), 0.f);
    t.y = fmaxf(fmaf(e0, w0.y, fmaf(e1, w1.y, p.y + q.y)), 0.f);
    t.z = fmaxf(fmaf(e0, w0.z, fmaf(e1, w1.z, p.z + q.z)), 0.f);
    t.w = fmaxf(fmaf(e0, w0.w, fmaf(e1, w1.w, p.w + q.w)), 0.f);
    float* dst = &S[(size_t)tgt * 256 + s_off + lane * 4];
    asm volatile("red.global.add.v4.f32 [%0], {%1,%2,%3,%4};"
                 :: "l"(dst), "f"(t.x), "f"(t.y), "f"(t.z), "f"(t.w) : "memory");
}

// ---------------- 128x128 tiled SGEMM, 8x8 micro-tile, reg-prefetch pipeline ----------------
// MODE 0 (PQ):      out[:, y*128:(y+1)*128] = h @ B[y] (+bias y==0,2); y==0 also zeroes S
// MODE 1 (COMBINE): u = S@[W2a;W2e] + h + dega*b2a + dege*b2e; h = LayerNorm(u)
// MODE 2 (COMB):    out = resid + relu(h @ B0 + bias0)
template <int MODE>
__global__ void __launch_bounds__(256) gemm_kernel(
    const float* __restrict__ A, int lda, int Ktot,
    const float* __restrict__ B0, const float* __restrict__ B1,
    const float* __restrict__ B2, const float* __restrict__ B3,
    const float* __restrict__ bias0, const float* __restrict__ bias2,
    const float* __restrict__ resid,
    const float* __restrict__ dega, const float* __restrict__ dege,
    const float* __restrict__ b2a, const float* __restrict__ b2e,
    const float* __restrict__ lng, const float* __restrict__ lnb,
    float* __restrict__ out, int ldo,
    float* __restrict__ Szero) {
    __shared__ __align__(16) float As[BK][BM + 4];
    __shared__ __align__(16) float Bs[BK][BN];

    int tid = threadIdx.x;
    int tx = tid & 15;   // col group (8 cols)
    int ty = tid >> 4;   // row group (8 rows)
    int row0 = blockIdx.x * BM;

    const float* B = B0;
    const float* bias = bias0;
    int ocol = 0;
    if (MODE == 0) {
        int y = blockIdx.y;
        B = (y == 0) ? B0 : (y == 1) ? B1 : (y == 2) ? B2 : B3;
        bias = (y == 0) ? bias0 : (y == 2) ? bias2 : nullptr;
        ocol = y * BN;
    }

    // A staging: thread loads 16 consecutive floats of one row (4 float4)
    int ar = tid >> 1;             // 0..127
    int ah = (tid & 1) * 16;       // k offset 0 or 16
    int agr = row0 + ar;
    bool aval = agr < NN;
    const float* Aptr = aval ? (A + (size_t)agr * lda + ah) : nullptr;
    // B staging: thread loads 4 float4, k = tid>>5 + 8i, col4 = tid&31
    int bk0 = tid >> 5;
    int bc = (tid & 31) * 4;

    float4 pa[4], pb[4];
    const float4 z4 = make_float4(0.f, 0.f, 0.f, 0.f);

    // prefetch kb = 0
    {
        const float* Bp = B;
        int kk = 0;
#pragma unroll
        for (int j = 0; j < 4; j++)
            pa[j] = aval ? *(const float4*)(Aptr + 0 + j * 4) : z4;
#pragma unroll
        for (int i = 0; i < 4; i++)
            pb[i] = *(const float4*)(Bp + (size_t)(kk + bk0 + i * 8) * H + bc);
    }

    float acc[8][8];
#pragma unroll
    for (int r = 0; r < 8; r++)
#pragma unroll
        for (int c = 0; c < 8; c++) acc[r][c] = 0.f;

    for (int kb = 0; kb < Ktot; kb += BK) {
        // commit staged regs to smem
#pragma unroll
        for (int j = 0; j < 4; j++) {
            int k0 = ah + j * 4;
            As[k0 + 0][ar] = pa[j].x;
            As[k0 + 1][ar] = pa[j].y;
            As[k0 + 2][ar] = pa[j].z;
            As[k0 + 3][ar] = pa[j].w;
        }
#pragma unroll
        for (int i = 0; i < 4; i++)
            *(float4*)&Bs[bk0 + i * 8][bc] = pb[i];
        __syncthreads();

        // prefetch next k-block
        int kb2 = kb + BK;
        if (kb2 < Ktot) {
            const float* Bp = B;
            int kk = kb2;
            if (MODE == 1 && kb2 >= H) { Bp = B1; kk = kb2 - H; }
#pragma unroll
            for (int j = 0; j < 4; j++)
                pa[j] = aval ? *(const float4*)(Aptr + kb2 + j * 4) : z4;
#pragma unroll
            for (int i = 0; i < 4; i++)
                pb[i] = *(const float4*)(Bp + (size_t)(kk + bk0 + i * 8) * H + bc);
        }

        // compute
#pragma unroll 8
        for (int k = 0; k < BK; k++) {
            float a[8], b[8];
            *(float4*)&a[0] = *(const float4*)&As[k][ty * 8];
            *(float4*)&a[4] = *(const float4*)&As[k][ty * 8 + 4];
            *(float4*)&b[0] = *(const float4*)&Bs[k][tx * 8];
            *(float4*)&b[4] = *(const float4*)&Bs[k][tx * 8 + 4];
#pragma unroll
            for (int r = 0; r < 8; r++)
#pragma unroll
                for (int c = 0; c < 8; c++) acc[r][c] = fmaf(a[r], b[c], acc[r][c]);
        }
        __syncthreads();
    }

    int col0 = tx * 8;
    if (MODE == 0) {
        float bv[8];
#pragma unroll
        for (int c = 0; c < 8; c++) bv[c] = bias ? bias[col0 + c] : 0.f;
#pragma unroll
        for (int r = 0; r < 8; r++) {
            int gr = row0 + ty * 8 + r;
            if (gr < NN) {
                float o[8];
#pragma unroll
                for (int c = 0; c < 8; c++) o[c] = acc[r][c] + bv[c];
                *(float4*)&out[(size_t)gr * ldo + ocol + col0] = *(float4*)o;
                *(float4*)&out[(size_t)gr * ldo + ocol + col0 + 4] = *(float4*)(o + 4);
            }
        }
        // y==0 blocks also zero the S buffer rows (fused, overlapped with other y work)
        if (blockIdx.y == 0 && Szero) {
#pragma unroll
            for (int r = 0; r < 8; r++) {
                int gr = row0 + ty * 8 + r;
                if (gr < NN) {
                    float4* dst = (float4*)&Szero[(size_t)gr * 256 + tx * 16];
                    dst[0] = z4; dst[1] = z4; dst[2] = z4; dst[3] = z4;
                }
            }
        }
    } else if (MODE == 2) {
        float bv[8];
#pragma unroll
        for (int c = 0; c < 8; c++) bv[c] = bias0[col0 + c];
#pragma unroll
        for (int r = 0; r < 8; r++) {
            int gr = row0 + ty * 8 + r;
            if (gr < NN) {
                float o[8];
#pragma unroll
                for (int c = 0; c < 8; c++) {
                    float v = fmaxf(acc[r][c] + bv[c], 0.f);
                    o[c] = v + resid[(size_t)gr * H + col0 + c];
                }
                *(float4*)&out[(size_t)gr * ldo + col0] = *(float4*)o;
                *(float4*)&out[(size_t)gr * ldo + col0 + 4] = *(float4*)(o + 4);
            }
        }
    } else {
        // MODE 1: residual + deg*b2, LayerNorm via half-warp shuffle reduction.
        // Row owners (same ty) are 16 consecutive lanes within one warp.
        float b2av[8], b2ev[8], gv[8], bbv[8];
        *(float4*)&b2av[0] = *(const float4*)&b2a[col0];
        *(float4*)&b2av[4] = *(const float4*)&b2a[col0 + 4];
        *(float4*)&b2ev[0] = *(const float4*)&b2e[col0];
        *(float4*)&b2ev[4] = *(const float4*)&b2e[col0 + 4];
        *(float4*)&gv[0] = *(const float4*)&lng[col0];
        *(float4*)&gv[4] = *(const float4*)&lng[col0 + 4];
        *(float4*)&bbv[0] = *(const float4*)&lnb[col0];
        *(float4*)&bbv[4] = *(const float4*)&lnb[col0 + 4];
#pragma unroll
        for (int r = 0; r < 8; r++) {
            int gr = row0 + ty * 8 + r;
            bool valid = gr < NN;
            float da = valid ? dega[gr] : 0.f;
            float de = valid ? dege[gr] : 0.f;
            float rs[8];
            if (valid) {
                *(float4*)&rs[0] = *(const float4*)&resid[(size_t)gr * H + col0];
                *(float4*)&rs[4] = *(const float4*)&resid[(size_t)gr * H + col0 + 4];
            } else {
#pragma unroll
                for (int c = 0; c < 8; c++) rs[c] = 0.f;
            }
            float v[8];
            float s = 0.f, s2 = 0.f;
#pragma unroll
            for (int c = 0; c < 8; c++) {
                v[c] = acc[r][c] + rs[c] + da * b2av[c] + de * b2ev[c];
                s += v[c];
                s2 += v[c] * v[c];
            }
#pragma unroll
            for (int off = 8; off; off >>= 1) {
                s += __shfl_xor_sync(0xffffffffu, s, off);
                s2 += __shfl_xor_sync(0xffffffffu, s2, off);
            }
            float mu = s * (1.f / 128.f);
            float var = s2 * (1.f / 128.f) - mu * mu;
            float rstd = rsqrtf(var + 1e-5f);
            if (valid) {
                float o[8];
#pragma unroll
                for (int c = 0; c < 8; c++) o[c] = (v[c] - mu) * rstd * gv[c] + bbv[c];
                *(float4*)&out[(size_t)gr * H + col0] = *(float4*)o;
                *(float4*)&out[(size_t)gr * H + col0 + 4] = *(float4*)(o + 4);
            }
        }
    }
}

// ---------------- launch ----------------
extern "C" void kernel_launch(void* const* d_in, const int* in_sizes, int n_in,
                              void* d_out, int out_size) {
    (void)in_sizes; (void)n_in; (void)out_size;
    const float* x       = (const float*)d_in[0];
    const int*   ally_ei = (const int*)d_in[1];
    const float* ally_ea = (const float*)d_in[2];
    const int*   enc_ei  = (const int*)d_in[3];
    const float* enc_ea  = (const float*)d_in[4];
    const float* W_in    = (const float*)d_in[5];
    const float* b_in    = (const float*)d_in[6];
    const float* ally_W1 = (const float*)d_in[7];
    const float* ally_b1 = (const float*)d_in[8];
    const float* ally_W2 = (const float*)d_in[9];
    const float* ally_b2 = (const float*)d_in[10];
    const float* enc_W1  = (const float*)d_in[11];
    const float* enc_b1  = (const float*)d_in[12];
    const float* enc_W2  = (const float*)d_in[13];
    const float* enc_b2  = (const float*)d_in[14];
    const float* ln_g    = (const float*)d_in[15];
    const float* ln_b    = (const float*)d_in[16];
    const float* comb_W  = (const float*)d_in[17];
    const float* comb_b  = (const float*)d_in[18];
    float* out = (float*)d_out;

    float *h, *PQ, *S, *deg;
    cudaGetSymbolAddress((void**)&h, g_h);
    cudaGetSymbolAddress((void**)&PQ, g_PQ);
    cudaGetSymbolAddress((void**)&S, g_S);
    cudaGetSymbolAddress((void**)&deg, g_deg);
    float* dega = deg;
    float* dege = deg + NN;

    const int nblk = (NN + BM - 1) / BM;  // 782

    // degree (recomputed every call for determinism)
    fill_zero<<<64, 256>>>((float4*)deg, 2 * NN / 4);
    deg_kernel<<<(2 * NE + 255) / 256, 256>>>(ally_ei, enc_ei, deg);

    // input projection
    input_proj<<<NN / IPN, 128>>>(x, W_in, b_in, h);

    for (int i = 0; i < 2; i++) {
        const float* aW1 = ally_W1 + (size_t)i * 258 * H;
        const float* eW1 = enc_W1 + (size_t)i * 258 * H;

        // P/Q for both edge types; y==0 blocks additionally zero S
        gemm_kernel<0><<<dim3(nblk, 4), 256>>>(
            h, H, H,
            aW1, aW1 + 128 * H, eW1, eW1 + 128 * H,
            ally_b1 + i * H, enc_b1 + i * H,
            nullptr, nullptr, nullptr, nullptr, nullptr, nullptr, nullptr,
            PQ, 4 * H, S);

        // edge scatter for both edge sets in one launch (2E warps)
        edge_kernel<<<2 * NE / 8, 256>>>(ally_ei, ally_ea, enc_ei, enc_ea,
                                         PQ, aW1 + 256 * H, eW1 + 256 * H, S);

        // combine: h = LN(h + S_a@W2a + dega*b2a + S_e@W2e + dege*b2e)
        gemm_kernel<1><<<nblk, 256>>>(
            S, 2 * H, 2 * H,
            ally_W2 + (size_t)i * H * H, enc_W2 + (size_t)i * H * H,
            nullptr, nullptr, nullptr, nullptr,
            h, dega, dege,
            ally_b2 + i * H, enc_b2 + i * H,
            ln_g + i * H, ln_b + i * H,
            h, H, nullptr);

        // comb MLP: h = h + relu(h @ comb_W + comb_b); last layer writes d_out
        float* dst = (i == 1) ? out : h;
        gemm_kernel<2><<<nblk, 256>>>(
            h, H, H,
            comb_W + (size_t)i * H * H, nullptr, nullptr, nullptr,
            comb_b + i * H, nullptr,
            h, nullptr, nullptr, nullptr, nullptr, nullptr, nullptr,
            dst, H, nullptr);
    }
}

// round 3
// speedup vs baseline: 1.4173x; 1.1615x over previous
#include <cuda_runtime.h>
#include <cstdint>
#include <cstddef>

#define NN 100000
#define NE 600000
#define H 128
#define FIN 39

#define BM 128
#define BN 128
#define BK 32

// ---------------- scratch (device globals; no allocation allowed) ----------------
__device__ float g_h[(size_t)NN * H];        // node features          [N,128]
__device__ float g_PQ[(size_t)NN * 4 * H];   // P_a|Q_a|P_e|Q_e        [N,512]
__device__ float g_S[(size_t)NN * 2 * H];    // S_ally | S_enc         [N,256]
__device__ float g_deg[2 * NN];              // deg_ally, deg_enc (as float)

__device__ __forceinline__ void cp16(uint32_t dst, const float* src) {
    asm volatile("cp.async.cg.shared.global [%0], [%1], 16;" :: "r"(dst), "l"(src));
}

// ---------------- utility kernels ----------------
__global__ void fill_zero(float4* __restrict__ p, int n4) {
    int i = blockIdx.x * blockDim.x + threadIdx.x;
    int stride = gridDim.x * blockDim.x;
    float4 z = make_float4(0.f, 0.f, 0.f, 0.f);
    for (; i < n4; i += stride) p[i] = z;
}

__global__ void deg_kernel(const int* __restrict__ eia, const int* __restrict__ eie,
                           float* __restrict__ deg) {
    int t = blockIdx.x * blockDim.x + threadIdx.x;
    if (t < NE) {
        atomicAdd(&deg[eia[NE + t]], 1.f);
    } else if (t < 2 * NE) {
        atomicAdd(&deg[NN + eie[NE + (t - NE)]], 1.f);
    }
}

// ---------------- input projection: h = relu(x @ W_in + b_in) ----------------
#define IPN 16
__global__ void __launch_bounds__(128) input_proj(const float* __restrict__ x,
                                                  const float* __restrict__ Win,
                                                  const float* __restrict__ bin,
                                                  float* __restrict__ h) {
    __shared__ float Ws[FIN * H];
    __shared__ float xs[IPN][FIN + 1];
    int tid = threadIdx.x;
    for (int i = tid; i < FIN * H; i += 128) Ws[i] = Win[i];
    int n0 = blockIdx.x * IPN;  // N divisible by 16
    for (int i = tid; i < IPN * FIN; i += 128) {
        int r = i / FIN, c = i - r * FIN;
        xs[r][c] = x[(size_t)(n0 + r) * FIN + c];
    }
    __syncthreads();
    float acc[IPN];
    float bv = bin[tid];
#pragma unroll
    for (int r = 0; r < IPN; r++) acc[r] = bv;
    for (int k = 0; k < FIN; k++) {
        float wv = Ws[k * H + tid];
#pragma unroll
        for (int r = 0; r < IPN; r++) acc[r] = fmaf(xs[r][k], wv, acc[r]);
    }
#pragma unroll
    for (int r = 0; r < IPN; r++)
        h[(size_t)(n0 + r) * H + tid] = fmaxf(acc[r], 0.f);
}

// ---------------- edge phase (both edge sets in one launch) ----------------
// warp per edge: S[tgt] += relu(P[tgt] + Q[src] + ea @ W1c)
__global__ void __launch_bounds__(256) edge_kernel(
    const int* __restrict__ eia, const float* __restrict__ eaa,
    const int* __restrict__ eie, const float* __restrict__ eae,
    const float* __restrict__ PQ,
    const float* __restrict__ w1ca, const float* __restrict__ w1ce,
    float* __restrict__ S) {
    __shared__ __align__(16) float w[512];
    w[threadIdx.x] = w1ca[threadIdx.x];
    w[256 + threadIdx.x] = w1ce[threadIdx.x];
    __syncthreads();
    unsigned gw = blockIdx.x * 8u + (threadIdx.x >> 5);
    int lane = threadIdx.x & 31;
    const int* ei;
    const float* ea;
    int pq_off, s_off, woff, e;
    if (gw < NE) {
        e = gw; ei = eia; ea = eaa; pq_off = 0; s_off = 0; woff = 0;
    } else {
        e = gw - NE; ei = eie; ea = eae; pq_off = 256; s_off = 128; woff = 256;
    }
    int src = ei[e];
    int tgt = ei[NE + e];
    float e0 = ea[2 * e], e1 = ea[2 * e + 1];
    float4 p = *(const float4*)&PQ[(size_t)tgt * 512 + pq_off + lane * 4];
    float4 q = *(const float4*)&PQ[(size_t)src * 512 + pq_off + 128 + lane * 4];
    float4 w0 = *(const float4*)&w[woff + lane * 4];
    float4 w1 = *(const float4*)&w[woff + H + lane * 4];
    float4 t;
    t.x = fmaxf(fmaf(e0, w0.x, fmaf(e1, w1.x, p.x + q.x)), 0.f);
    t.y = fmaxf(fmaf(e0, w0.y, fmaf(e1, w1.y, p.y + q.y)), 0.f);
    t.z = fmaxf(fmaf(e0, w0.z, fmaf(e1, w1.z, p.z + q.z)), 0.f);
    t.w = fmaxf(fmaf(e0, w0.w, fmaf(e1, w1.w, p.w + q.w)), 0.f);
    float* dst = &S[(size_t)tgt * 256 + s_off + lane * 4];
    asm volatile("red.global.add.v4.f32 [%0], {%1,%2,%3,%4};"
                 :: "l"(dst), "f"(t.x), "f"(t.y), "f"(t.z), "f"(t.w) : "memory");
}

// ---------------- 128x128 SGEMM, 128 threads, 16x8 micro-tile ----------------
// double-buffered smem; B staged via cp.async (k-major, no transpose);
// A register-staged + transposed store; ONE __syncthreads per k-block.
// MODE 0 (PQ):      out[:, y*128:(y+1)*128] = h @ B[y] (+bias y==0,2); y==0 zeroes S
// MODE 1 (COMBINE): u = S@[W2a;W2e] + h + dega*b2a + dege*b2e; h = LayerNorm(u)
// MODE 2 (COMB):    out = resid + relu(h @ B0 + bias0)
template <int MODE>
__global__ void __launch_bounds__(128, 2) gemm_kernel(
    const float* __restrict__ A, int lda, int Ktot,
    const float* __restrict__ B0, const float* __restrict__ B1,
    const float* __restrict__ B2, const float* __restrict__ B3,
    const float* __restrict__ bias0, const float* __restrict__ bias2,
    const float* __restrict__ resid,
    const float* __restrict__ dega, const float* __restrict__ dege,
    const float* __restrict__ b2a, const float* __restrict__ b2e,
    const float* __restrict__ lng, const float* __restrict__ lnb,
    float* __restrict__ out, int ldo,
    float* __restrict__ Szero) {
    extern __shared__ float sm[];
    float(*As)[BK][BM + 4] = (float(*)[BK][BM + 4])sm;                  // [2][32][132]
    float(*Bs)[BK][BN] = (float(*)[BK][BN])(sm + 2 * BK * (BM + 4));    // [2][32][128]

    int tid = threadIdx.x;
    int tx = tid & 15;   // col group (8 cols)
    int ty = tid >> 4;   // row group (16 rows)
    int row0 = blockIdx.x * BM;

    const float* B = B0;
    const float* bias = bias0;
    int ocol = 0;
    if (MODE == 0) {
        int y = blockIdx.y;
        B = (y == 0) ? B0 : (y == 1) ? B1 : (y == 2) ? B2 : B3;
        bias = (y == 0) ? bias0 : (y == 2) ? bias2 : nullptr;
        ocol = y * BN;
    }

    // A staging: one row per thread (32 floats = 8 float4), transposed store
    int agr = row0 + tid;
    bool aval = agr < NN;
    const float* Aptr = A + (size_t)(aval ? agr : 0) * lda;
    // B staging: per thread 4 k-rows (bk0+8i), 2 float4 each (8 cp.async)
    int bk0 = tid >> 4;        // 0..7
    int bc = (tid & 15) * 8;   // 0..120

    uint32_t bs_base = (uint32_t)__cvta_generic_to_shared(&Bs[0][0][0]);

    // prologue: B(0) -> buf0, A(0) -> regs
#pragma unroll
    for (int i = 0; i < 4; i++) {
        int k = bk0 + i * 8;
        const float* s = B + (size_t)k * H + bc;
        uint32_t d = bs_base + (unsigned)(k * BN + bc) * 4u;
        cp16(d, s);
        cp16(d + 16, s + 4);
    }
    asm volatile("cp.async.commit_group;" ::: "memory");

    float4 pa[8];
#pragma unroll
    for (int j = 0; j < 8; j++) pa[j] = *(const float4*)(Aptr + j * 4);

    float acc[16][8];
#pragma unroll
    for (int r = 0; r < 16; r++)
#pragma unroll
        for (int c = 0; c < 8; c++) acc[r][c] = 0.f;

    const int niter = Ktot / BK;
    for (int it = 0; it < niter; it++) {
        int buf = it & 1;
        asm volatile("cp.async.wait_group 0;" ::: "memory");
        // commit A regs -> As[buf] (transposed)
#pragma unroll
        for (int j = 0; j < 8; j++) {
            int k0 = j * 4;
            As[buf][k0 + 0][tid] = pa[j].x;
            As[buf][k0 + 1][tid] = pa[j].y;
            As[buf][k0 + 2][tid] = pa[j].z;
            As[buf][k0 + 3][tid] = pa[j].w;
        }
        // prefetch next A into regs
        if (it + 1 < niter) {
            const float* ap = Aptr + (it + 1) * BK;
#pragma unroll
            for (int j = 0; j < 8; j++) pa[j] = *(const float4*)(ap + j * 4);
        }
        __syncthreads();
        // issue next B tile into the other buffer
        if (it + 1 < niter) {
            int kb2 = (it + 1) * BK;
            const float* Bp = B;
            int kk = kb2;
            if (MODE == 1 && kb2 >= H) { Bp = B1; kk = kb2 - H; }
            uint32_t bb = bs_base + (unsigned)((buf ^ 1) * BK * BN) * 4u;
#pragma unroll
            for (int i = 0; i < 4; i++) {
                int k = bk0 + i * 8;
                const float* s = Bp + (size_t)(kk + k) * H + bc;
                uint32_t d = bb + (unsigned)(k * BN + bc) * 4u;
                cp16(d, s);
                cp16(d + 16, s + 4);
            }
            asm volatile("cp.async.commit_group;" ::: "memory");
        }
        // compute
#pragma unroll 4
        for (int k = 0; k < BK; k++) {
            float a[16], b[8];
            *(float4*)&a[0] = *(const float4*)&As[buf][k][ty * 16];
            *(float4*)&a[4] = *(const float4*)&As[buf][k][ty * 16 + 4];
            *(float4*)&a[8] = *(const float4*)&As[buf][k][ty * 16 + 8];
            *(float4*)&a[12] = *(const float4*)&As[buf][k][ty * 16 + 12];
            *(float4*)&b[0] = *(const float4*)&Bs[buf][k][tx * 8];
            *(float4*)&b[4] = *(const float4*)&Bs[buf][k][tx * 8 + 4];
#pragma unroll
            for (int r = 0; r < 16; r++)
#pragma unroll
                for (int c = 0; c < 8; c++) acc[r][c] = fmaf(a[r], b[c], acc[r][c]);
        }
    }

    int col0 = tx * 8;
    const float4 z4 = make_float4(0.f, 0.f, 0.f, 0.f);
    if (MODE == 0) {
        float bv[8];
#pragma unroll
        for (int c = 0; c < 8; c++) bv[c] = bias ? bias[col0 + c] : 0.f;
#pragma unroll
        for (int r = 0; r < 16; r++) {
            int gr = row0 + ty * 16 + r;
            if (gr < NN) {
                float o[8];
#pragma unroll
                for (int c = 0; c < 8; c++) o[c] = acc[r][c] + bv[c];
                *(float4*)&out[(size_t)gr * ldo + ocol + col0] = *(float4*)o;
                *(float4*)&out[(size_t)gr * ldo + ocol + col0 + 4] = *(float4*)(o + 4);
            }
        }
        // y==0 blocks zero the S buffer rows (fused, overlapped with other y work)
        if (blockIdx.y == 0 && Szero) {
#pragma unroll
            for (int r = 0; r < 16; r++) {
                int gr = row0 + ty * 16 + r;
                if (gr < NN) {
                    float4* dst = (float4*)&Szero[(size_t)gr * 256 + tx * 16];
                    dst[0] = z4; dst[1] = z4; dst[2] = z4; dst[3] = z4;
                }
            }
        }
    } else if (MODE == 2) {
        float bv[8];
#pragma unroll
        for (int c = 0; c < 8; c++) bv[c] = bias0[col0 + c];
#pragma unroll
        for (int r = 0; r < 16; r++) {
            int gr = row0 + ty * 16 + r;
            if (gr < NN) {
                float o[8];
#pragma unroll
                for (int c = 0; c < 8; c++) {
                    float v = fmaxf(acc[r][c] + bv[c], 0.f);
                    o[c] = v + resid[(size_t)gr * H + col0 + c];
                }
                *(float4*)&out[(size_t)gr * ldo + col0] = *(float4*)o;
                *(float4*)&out[(size_t)gr * ldo + col0 + 4] = *(float4*)(o + 4);
            }
        }
    } else {
        // MODE 1: residual + deg*b2, LayerNorm via 16-lane shuffle reduction
        float b2av[8], b2ev[8], gv[8], bbv[8];
        *(float4*)&b2av[0] = *(const float4*)&b2a[col0];
        *(float4*)&b2av[4] = *(const float4*)&b2a[col0 + 4];
        *(float4*)&b2ev[0] = *(const float4*)&b2e[col0];
        *(float4*)&b2ev[4] = *(const float4*)&b2e[col0 + 4];
        *(float4*)&gv[0] = *(const float4*)&lng[col0];
        *(float4*)&gv[4] = *(const float4*)&lng[col0 + 4];
        *(float4*)&bbv[0] = *(const float4*)&lnb[col0];
        *(float4*)&bbv[4] = *(const float4*)&lnb[col0 + 4];
#pragma unroll
        for (int r = 0; r < 16; r++) {
            int gr = row0 + ty * 16 + r;
            bool valid = gr < NN;
            float da = valid ? dega[gr] : 0.f;
            float de = valid ? dege[gr] : 0.f;
            float rs[8];
            if (valid) {
                *(float4*)&rs[0] = *(const float4*)&resid[(size_t)gr * H + col0];
                *(float4*)&rs[4] = *(const float4*)&resid[(size_t)gr * H + col0 + 4];
            } else {
#pragma unroll
                for (int c = 0; c < 8; c++) rs[c] = 0.f;
            }
            float v[8];
            float s = 0.f, s2 = 0.f;
#pragma unroll
            for (int c = 0; c < 8; c++) {
                v[c] = acc[r][c] + rs[c] + da * b2av[c] + de * b2ev[c];
                s += v[c];
                s2 += v[c] * v[c];
            }
#pragma unroll
            for (int off = 8; off; off >>= 1) {
                s += __shfl_xor_sync(0xffffffffu, s, off);
                s2 += __shfl_xor_sync(0xffffffffu, s2, off);
            }
            float mu = s * (1.f / 128.f);
            float var = s2 * (1.f / 128.f) - mu * mu;
            float rstd = rsqrtf(var + 1e-5f);
            if (valid) {
                float o[8];
#pragma unroll
                for (int c = 0; c < 8; c++) o[c] = (v[c] - mu) * rstd * gv[c] + bbv[c];
                *(float4*)&out[(size_t)gr * H + col0] = *(float4*)o;
                *(float4*)&out[(size_t)gr * H + col0 + 4] = *(float4*)(o + 4);
            }
        }
    }
}

// ---------------- launch ----------------
extern "C" void kernel_launch(void* const* d_in, const int* in_sizes, int n_in,
                              void* d_out, int out_size) {
    (void)in_sizes; (void)n_in; (void)out_size;
    const float* x       = (const float*)d_in[0];
    const int*   ally_ei = (const int*)d_in[1];
    const float* ally_ea = (const float*)d_in[2];
    const int*   enc_ei  = (const int*)d_in[3];
    const float* enc_ea  = (const float*)d_in[4];
    const float* W_in    = (const float*)d_in[5];
    const float* b_in    = (const float*)d_in[6];
    const float* ally_W1 = (const float*)d_in[7];
    const float* ally_b1 = (const float*)d_in[8];
    const float* ally_W2 = (const float*)d_in[9];
    const float* ally_b2 = (const float*)d_in[10];
    const float* enc_W1  = (const float*)d_in[11];
    const float* enc_b1  = (const float*)d_in[12];
    const float* enc_W2  = (const float*)d_in[13];
    const float* enc_b2  = (const float*)d_in[14];
    const float* ln_g    = (const float*)d_in[15];
    const float* ln_b    = (const float*)d_in[16];
    const float* comb_W  = (const float*)d_in[17];
    const float* comb_b  = (const float*)d_in[18];
    float* out = (float*)d_out;

    float *h, *PQ, *S, *deg;
    cudaGetSymbolAddress((void**)&h, g_h);
    cudaGetSymbolAddress((void**)&PQ, g_PQ);
    cudaGetSymbolAddress((void**)&S, g_S);
    cudaGetSymbolAddress((void**)&deg, g_deg);
    float* dega = deg;
    float* dege = deg + NN;

    const int SMEM = (2 * BK * (BM + 4) + 2 * BK * BN) * 4;  // 66560 B
    cudaFuncSetAttribute(gemm_kernel<0>, cudaFuncAttributeMaxDynamicSharedMemorySize, SMEM);
    cudaFuncSetAttribute(gemm_kernel<1>, cudaFuncAttributeMaxDynamicSharedMemorySize, SMEM);
    cudaFuncSetAttribute(gemm_kernel<2>, cudaFuncAttributeMaxDynamicSharedMemorySize, SMEM);

    const int nblk = (NN + BM - 1) / BM;  // 782

    // degree (recomputed every call for determinism)
    fill_zero<<<64, 256>>>((float4*)deg, 2 * NN / 4);
    deg_kernel<<<(2 * NE + 255) / 256, 256>>>(ally_ei, enc_ei, deg);

    // input projection
    input_proj<<<NN / IPN, 128>>>(x, W_in, b_in, h);

    for (int i = 0; i < 2; i++) {
        const float* aW1 = ally_W1 + (size_t)i * 258 * H;
        const float* eW1 = enc_W1 + (size_t)i * 258 * H;

        // P/Q for both edge types; y==0 blocks additionally zero S
        gemm_kernel<0><<<dim3(nblk, 4), 128, SMEM>>>(
            h, H, H,
            aW1, aW1 + 128 * H, eW1, eW1 + 128 * H,
            ally_b1 + i * H, enc_b1 + i * H,
            nullptr, nullptr, nullptr, nullptr, nullptr, nullptr, nullptr,
            PQ, 4 * H, S);

        // edge scatter for both edge sets in one launch (2E warps)
        edge_kernel<<<2 * NE / 8, 256>>>(ally_ei, ally_ea, enc_ei, enc_ea,
                                         PQ, aW1 + 256 * H, eW1 + 256 * H, S);

        // combine: h = LN(h + S_a@W2a + dega*b2a + S_e@W2e + dege*b2e)
        gemm_kernel<1><<<nblk, 128, SMEM>>>(
            S, 2 * H, 2 * H,
            ally_W2 + (size_t)i * H * H, enc_W2 + (size_t)i * H * H,
            nullptr, nullptr, nullptr, nullptr,
            h, dega, dege,
            ally_b2 + i * H, enc_b2 + i * H,
            ln_g + i * H, ln_b + i * H,
            h, H, nullptr);

        // comb MLP: h = h + relu(h @ comb_W + comb_b); last layer writes d_out
        float* dst = (i == 1) ? out : h;
        gemm_kernel<2><<<nblk, 128, SMEM>>>(
            h, H, H,
            comb_W + (size_t)i * H * H, nullptr, nullptr, nullptr,
            comb_b + i * H, nullptr,
            h, nullptr, nullptr, nullptr, nullptr, nullptr, nullptr,
            dst, H, nullptr);
    }
}

// round 4
// speedup vs baseline: 1.5341x; 1.0824x over previous
#include <cuda_runtime.h>
#include <cstdint>
#include <cstddef>

#define NN 100000
#define NE 600000
#define H 128
#define FIN 39

#define BM 128
#define BN 128
#define BK 32

// ---------------- scratch (device globals; no allocation allowed) ----------------
__device__ float g_h[(size_t)NN * H];        // node features          [N,128]
__device__ float g_PQ[(size_t)NN * 4 * H];   // P_a|Q_a|P_e|Q_e        [N,512]
__device__ float g_S[(size_t)NN * 2 * H];    // S_ally | S_enc         [N,256]
__device__ float g_deg[2 * NN];              // deg_ally, deg_enc (as float)

__device__ __forceinline__ void cp16(uint32_t dst, const float* src) {
    asm volatile("cp.async.cg.shared.global [%0], [%1], 16;" :: "r"(dst), "l"(src));
}
// packed f32x2 fma: d = a*b + d (element-wise on the two packed floats)
__device__ __forceinline__ void ffma2(unsigned long long& d, unsigned long long a,
                                      unsigned long long b) {
    asm("fma.rn.f32x2 %0, %1, %2, %0;" : "+l"(d) : "l"(a), "l"(b));
}
__device__ __forceinline__ unsigned long long pack2(float x) {
    unsigned long long r;
    asm("mov.b64 %0, {%1, %1};" : "=l"(r) : "f"(x));
    return r;
}
__device__ __forceinline__ void unpack2(unsigned long long v, float& lo, float& hi) {
    asm("mov.b64 {%0, %1}, %2;" : "=f"(lo), "=f"(hi) : "l"(v));
}

// ---------------- utility kernels ----------------
__global__ void fill_zero(float4* __restrict__ p, int n4) {
    int i = blockIdx.x * blockDim.x + threadIdx.x;
    int stride = gridDim.x * blockDim.x;
    float4 z = make_float4(0.f, 0.f, 0.f, 0.f);
    for (; i < n4; i += stride) p[i] = z;
}

__global__ void deg_kernel(const int* __restrict__ eia, const int* __restrict__ eie,
                           float* __restrict__ deg) {
    int t = blockIdx.x * blockDim.x + threadIdx.x;
    if (t < NE) {
        atomicAdd(&deg[eia[NE + t]], 1.f);
    } else if (t < 2 * NE) {
        atomicAdd(&deg[NN + eie[NE + (t - NE)]], 1.f);
    }
}

// ---------------- input projection: h = relu(x @ W_in + b_in) ----------------
#define IPN 16
__global__ void __launch_bounds__(128) input_proj(const float* __restrict__ x,
                                                  const float* __restrict__ Win,
                                                  const float* __restrict__ bin,
                                                  float* __restrict__ h) {
    __shared__ float Ws[FIN * H];
    __shared__ float xs[IPN][FIN + 1];
    int tid = threadIdx.x;
    for (int i = tid; i < FIN * H; i += 128) Ws[i] = Win[i];
    int n0 = blockIdx.x * IPN;  // N divisible by 16
    for (int i = tid; i < IPN * FIN; i += 128) {
        int r = i / FIN, c = i - r * FIN;
        xs[r][c] = x[(size_t)(n0 + r) * FIN + c];
    }
    __syncthreads();
    float acc[IPN];
    float bv = bin[tid];
#pragma unroll
    for (int r = 0; r < IPN; r++) acc[r] = bv;
    for (int k = 0; k < FIN; k++) {
        float wv = Ws[k * H + tid];
#pragma unroll
        for (int r = 0; r < IPN; r++) acc[r] = fmaf(xs[r][k], wv, acc[r]);
    }
#pragma unroll
    for (int r = 0; r < IPN; r++)
        h[(size_t)(n0 + r) * H + tid] = fmaxf(acc[r], 0.f);
}

// ---------------- edge phase (both edge sets in one launch) ----------------
// warp per edge: S[tgt] += relu(P[tgt] + Q[src] + ea @ W1c)
__global__ void __launch_bounds__(256) edge_kernel(
    const int* __restrict__ eia, const float* __restrict__ eaa,
    const int* __restrict__ eie, const float* __restrict__ eae,
    const float* __restrict__ PQ,
    const float* __restrict__ w1ca, const float* __restrict__ w1ce,
    float* __restrict__ S) {
    __shared__ __align__(16) float w[512];
    w[threadIdx.x] = w1ca[threadIdx.x];
    w[256 + threadIdx.x] = w1ce[threadIdx.x];
    __syncthreads();
    unsigned gw = blockIdx.x * 8u + (threadIdx.x >> 5);
    int lane = threadIdx.x & 31;
    const int* ei;
    const float* ea;
    int pq_off, s_off, woff, e;
    if (gw < NE) {
        e = gw; ei = eia; ea = eaa; pq_off = 0; s_off = 0; woff = 0;
    } else {
        e = gw - NE; ei = eie; ea = eae; pq_off = 256; s_off = 128; woff = 256;
    }
    int src = ei[e];
    int tgt = ei[NE + e];
    float e0 = ea[2 * e], e1 = ea[2 * e + 1];
    float4 p = *(const float4*)&PQ[(size_t)tgt * 512 + pq_off + lane * 4];
    float4 q = *(const float4*)&PQ[(size_t)src * 512 + pq_off + 128 + lane * 4];
    float4 w0 = *(const float4*)&w[woff + lane * 4];
    float4 w1 = *(const float4*)&w[woff + H + lane * 4];
    float4 t;
    t.x = fmaxf(fmaf(e0, w0.x, fmaf(e1, w1.x, p.x + q.x)), 0.f);
    t.y = fmaxf(fmaf(e0, w0.y, fmaf(e1, w1.y, p.y + q.y)), 0.f);
    t.z = fmaxf(fmaf(e0, w0.z, fmaf(e1, w1.z, p.z + q.z)), 0.f);
    t.w = fmaxf(fmaf(e0, w0.w, fmaf(e1, w1.w, p.w + q.w)), 0.f);
    float* dst = &S[(size_t)tgt * 256 + s_off + lane * 4];
    asm volatile("red.global.add.v4.f32 [%0], {%1,%2,%3,%4};"
                 :: "l"(dst), "f"(t.x), "f"(t.y), "f"(t.z), "f"(t.w) : "memory");
}

// ---------------- 128x128 SGEMM, 128 threads, 16x8 micro-tile, FFMA2 inner loop ----------------
// Accumulators packed as f32x2 over ROW pairs: acc[rp][c] holds rows (2rp, 2rp+1), col c.
// double-buffered smem; B staged via cp.async; A register-staged + transposed store.
// MODE 0 (PQ):      out[:, y*128:(y+1)*128] = h @ B[y] (+bias y==0,2); y==0 zeroes S
// MODE 1 (COMBINE): u = S@[W2a;W2e] + h + dega*b2a + dege*b2e; h = LayerNorm(u)
// MODE 2 (COMB):    out = resid + relu(h @ B0 + bias0)
template <int MODE>
__global__ void __launch_bounds__(128, 2) gemm_kernel(
    const float* __restrict__ A, int lda, int Ktot,
    const float* __restrict__ B0, const float* __restrict__ B1,
    const float* __restrict__ B2, const float* __restrict__ B3,
    const float* __restrict__ bias0, const float* __restrict__ bias2,
    const float* __restrict__ resid,
    const float* __restrict__ dega, const float* __restrict__ dege,
    const float* __restrict__ b2a, const float* __restrict__ b2e,
    const float* __restrict__ lng, const float* __restrict__ lnb,
    float* __restrict__ out, int ldo,
    float* __restrict__ Szero) {
    extern __shared__ float sm[];
    float(*As)[BK][BM + 4] = (float(*)[BK][BM + 4])sm;                  // [2][32][132]
    float(*Bs)[BK][BN] = (float(*)[BK][BN])(sm + 2 * BK * (BM + 4));    // [2][32][128]

    int tid = threadIdx.x;
    int tx = tid & 15;   // col group (8 cols)
    int ty = tid >> 4;   // row group (16 rows)
    int row0 = blockIdx.x * BM;

    const float* B = B0;
    const float* bias = bias0;
    int ocol = 0;
    if (MODE == 0) {
        int y = blockIdx.y;
        B = (y == 0) ? B0 : (y == 1) ? B1 : (y == 2) ? B2 : B3;
        bias = (y == 0) ? bias0 : (y == 2) ? bias2 : nullptr;
        ocol = y * BN;
    }

    // A staging: one row per thread (32 floats = 8 float4), transposed store
    int agr = row0 + tid;
    bool aval = agr < NN;
    const float* Aptr = A + (size_t)(aval ? agr : 0) * lda;
    // B staging: per thread 4 k-rows (bk0+8i), 2 float4 each (8 cp.async)
    int bk0 = tid >> 4;        // 0..7
    int bc = (tid & 15) * 8;   // 0..120

    uint32_t bs_base = (uint32_t)__cvta_generic_to_shared(&Bs[0][0][0]);

    // prologue: B(0) -> buf0, A(0) -> regs
#pragma unroll
    for (int i = 0; i < 4; i++) {
        int k = bk0 + i * 8;
        const float* s = B + (size_t)k * H + bc;
        uint32_t d = bs_base + (unsigned)(k * BN + bc) * 4u;
        cp16(d, s);
        cp16(d + 16, s + 4);
    }
    asm volatile("cp.async.commit_group;" ::: "memory");

    float4 pa[8];
#pragma unroll
    for (int j = 0; j < 8; j++) pa[j] = *(const float4*)(Aptr + j * 4);

    unsigned long long acc[8][8];  // row-pair x col, packed f32x2
#pragma unroll
    for (int rp = 0; rp < 8; rp++)
#pragma unroll
        for (int c = 0; c < 8; c++) acc[rp][c] = 0ull;

    const int niter = Ktot / BK;
    for (int it = 0; it < niter; it++) {
        int buf = it & 1;
        asm volatile("cp.async.wait_group 0;" ::: "memory");
        // commit A regs -> As[buf] (transposed)
#pragma unroll
        for (int j = 0; j < 8; j++) {
            int k0 = j * 4;
            As[buf][k0 + 0][tid] = pa[j].x;
            As[buf][k0 + 1][tid] = pa[j].y;
            As[buf][k0 + 2][tid] = pa[j].z;
            As[buf][k0 + 3][tid] = pa[j].w;
        }
        // prefetch next A into regs
        if (it + 1 < niter) {
            const float* ap = Aptr + (it + 1) * BK;
#pragma unroll
            for (int j = 0; j < 8; j++) pa[j] = *(const float4*)(ap + j * 4);
        }
        __syncthreads();
        // issue next B tile into the other buffer
        if (it + 1 < niter) {
            int kb2 = (it + 1) * BK;
            const float* Bp = B;
            int kk = kb2;
            if (MODE == 1 && kb2 >= H) { Bp = B1; kk = kb2 - H; }
            uint32_t bb = bs_base + (unsigned)((buf ^ 1) * BK * BN) * 4u;
#pragma unroll
            for (int i = 0; i < 4; i++) {
                int k = bk0 + i * 8;
                const float* s = Bp + (size_t)(kk + k) * H + bc;
                uint32_t d = bb + (unsigned)(k * BN + bc) * 4u;
                cp16(d, s);
                cp16(d + 16, s + 4);
            }
            asm volatile("cp.async.commit_group;" ::: "memory");
        }
        // compute: FFMA2, rows packed in pairs
#pragma unroll 4
        for (int k = 0; k < BK; k++) {
            unsigned long long a2[8];
            const ulonglong2* arow = (const ulonglong2*)&As[buf][k][ty * 16];
#pragma unroll
            for (int j = 0; j < 4; j++) {
                ulonglong2 v = arow[j];
                a2[j * 2] = v.x;
                a2[j * 2 + 1] = v.y;
            }
            float b[8];
            *(float4*)&b[0] = *(const float4*)&Bs[buf][k][tx * 8];
            *(float4*)&b[4] = *(const float4*)&Bs[buf][k][tx * 8 + 4];
            unsigned long long bp[8];
#pragma unroll
            for (int c = 0; c < 8; c++) bp[c] = pack2(b[c]);
#pragma unroll
            for (int rp = 0; rp < 8; rp++)
#pragma unroll
                for (int c = 0; c < 8; c++) ffma2(acc[rp][c], a2[rp], bp[c]);
        }
    }

    int col0 = tx * 8;
    const float4 z4 = make_float4(0.f, 0.f, 0.f, 0.f);

    if (MODE == 0) {
        float bv[8];
#pragma unroll
        for (int c = 0; c < 8; c++) bv[c] = bias ? bias[col0 + c] : 0.f;
#pragma unroll
        for (int rp = 0; rp < 8; rp++) {
            float vlo[8], vhi[8];
#pragma unroll
            for (int c = 0; c < 8; c++) unpack2(acc[rp][c], vlo[c], vhi[c]);
            int gr0 = row0 + ty * 16 + rp * 2;
#pragma unroll
            for (int h2 = 0; h2 < 2; h2++) {
                int gr = gr0 + h2;
                const float* v = h2 ? vhi : vlo;
                if (gr < NN) {
                    float o[8];
#pragma unroll
                    for (int c = 0; c < 8; c++) o[c] = v[c] + bv[c];
                    *(float4*)&out[(size_t)gr * ldo + ocol + col0] = *(float4*)o;
                    *(float4*)&out[(size_t)gr * ldo + ocol + col0 + 4] = *(float4*)(o + 4);
                }
            }
        }
        if (blockIdx.y == 0 && Szero) {
#pragma unroll
            for (int r = 0; r < 16; r++) {
                int gr = row0 + ty * 16 + r;
                if (gr < NN) {
                    float4* dst = (float4*)&Szero[(size_t)gr * 256 + tx * 16];
                    dst[0] = z4; dst[1] = z4; dst[2] = z4; dst[3] = z4;
                }
            }
        }
    } else if (MODE == 2) {
        float bv[8];
#pragma unroll
        for (int c = 0; c < 8; c++) bv[c] = bias0[col0 + c];
#pragma unroll
        for (int rp = 0; rp < 8; rp++) {
            float vlo[8], vhi[8];
#pragma unroll
            for (int c = 0; c < 8; c++) unpack2(acc[rp][c], vlo[c], vhi[c]);
            int gr0 = row0 + ty * 16 + rp * 2;
#pragma unroll
            for (int h2 = 0; h2 < 2; h2++) {
                int gr = gr0 + h2;
                const float* v = h2 ? vhi : vlo;
                if (gr < NN) {
                    float o[8];
#pragma unroll
                    for (int c = 0; c < 8; c++) {
                        float t = fmaxf(v[c] + bv[c], 0.f);
                        o[c] = t + resid[(size_t)gr * H + col0 + c];
                    }
                    *(float4*)&out[(size_t)gr * ldo + col0] = *(float4*)o;
                    *(float4*)&out[(size_t)gr * ldo + col0 + 4] = *(float4*)(o + 4);
                }
            }
        }
    } else {
        // MODE 1: residual + deg*b2, LayerNorm via 16-lane shuffle reduction
        float b2av[8], b2ev[8], gv[8], bbv[8];
        *(float4*)&b2av[0] = *(const float4*)&b2a[col0];
        *(float4*)&b2av[4] = *(const float4*)&b2a[col0 + 4];
        *(float4*)&b2ev[0] = *(const float4*)&b2e[col0];
        *(float4*)&b2ev[4] = *(const float4*)&b2e[col0 + 4];
        *(float4*)&gv[0] = *(const float4*)&lng[col0];
        *(float4*)&gv[4] = *(const float4*)&lng[col0 + 4];
        *(float4*)&bbv[0] = *(const float4*)&lnb[col0];
        *(float4*)&bbv[4] = *(const float4*)&lnb[col0 + 4];
#pragma unroll
        for (int rp = 0; rp < 8; rp++) {
            float vlo[8], vhi[8];
#pragma unroll
            for (int c = 0; c < 8; c++) unpack2(acc[rp][c], vlo[c], vhi[c]);
            int gr0 = row0 + ty * 16 + rp * 2;
#pragma unroll
            for (int h2 = 0; h2 < 2; h2++) {
                int gr = gr0 + h2;
                float* vv = h2 ? vhi : vlo;
                bool valid = gr < NN;
                float da = valid ? dega[gr] : 0.f;
                float de = valid ? dege[gr] : 0.f;
                float rs[8];
                if (valid) {
                    *(float4*)&rs[0] = *(const float4*)&resid[(size_t)gr * H + col0];
                    *(float4*)&rs[4] = *(const float4*)&resid[(size_t)gr * H + col0 + 4];
                } else {
#pragma unroll
                    for (int c = 0; c < 8; c++) rs[c] = 0.f;
                }
                float v[8];
                float s = 0.f, s2 = 0.f;
#pragma unroll
                for (int c = 0; c < 8; c++) {
                    v[c] = vv[c] + rs[c] + da * b2av[c] + de * b2ev[c];
                    s += v[c];
                    s2 += v[c] * v[c];
                }
#pragma unroll
                for (int off = 8; off; off >>= 1) {
                    s += __shfl_xor_sync(0xffffffffu, s, off);
                    s2 += __shfl_xor_sync(0xffffffffu, s2, off);
                }
                float mu = s * (1.f / 128.f);
                float var = s2 * (1.f / 128.f) - mu * mu;
                float rstd = rsqrtf(var + 1e-5f);
                if (valid) {
                    float o[8];
#pragma unroll
                    for (int c = 0; c < 8; c++) o[c] = (v[c] - mu) * rstd * gv[c] + bbv[c];
                    *(float4*)&out[(size_t)gr * H + col0] = *(float4*)o;
                    *(float4*)&out[(size_t)gr * H + col0 + 4] = *(float4*)(o + 4);
                }
            }
        }
    }
}

// ---------------- launch ----------------
extern "C" void kernel_launch(void* const* d_in, const int* in_sizes, int n_in,
                              void* d_out, int out_size) {
    (void)in_sizes; (void)n_in; (void)out_size;
    const float* x       = (const float*)d_in[0];
    const int*   ally_ei = (const int*)d_in[1];
    const float* ally_ea = (const float*)d_in[2];
    const int*   enc_ei  = (const int*)d_in[3];
    const float* enc_ea  = (const float*)d_in[4];
    const float* W_in    = (const float*)d_in[5];
    const float* b_in    = (const float*)d_in[6];
    const float* ally_W1 = (const float*)d_in[7];
    const float* ally_b1 = (const float*)d_in[8];
    const float* ally_W2 = (const float*)d_in[9];
    const float* ally_b2 = (const float*)d_in[10];
    const float* enc_W1  = (const float*)d_in[11];
    const float* enc_b1  = (const float*)d_in[12];
    const float* enc_W2  = (const float*)d_in[13];
    const float* enc_b2  = (const float*)d_in[14];
    const float* ln_g    = (const float*)d_in[15];
    const float* ln_b    = (const float*)d_in[16];
    const float* comb_W  = (const float*)d_in[17];
    const float* comb_b  = (const float*)d_in[18];
    float* out = (float*)d_out;

    float *h, *PQ, *S, *deg;
    cudaGetSymbolAddress((void**)&h, g_h);
    cudaGetSymbolAddress((void**)&PQ, g_PQ);
    cudaGetSymbolAddress((void**)&S, g_S);
    cudaGetSymbolAddress((void**)&deg, g_deg);
    float* dega = deg;
    float* dege = deg + NN;

    const int SMEM = (2 * BK * (BM + 4) + 2 * BK * BN) * 4;  // 66560 B
    cudaFuncSetAttribute(gemm_kernel<0>, cudaFuncAttributeMaxDynamicSharedMemorySize, SMEM);
    cudaFuncSetAttribute(gemm_kernel<1>, cudaFuncAttributeMaxDynamicSharedMemorySize, SMEM);
    cudaFuncSetAttribute(gemm_kernel<2>, cudaFuncAttributeMaxDynamicSharedMemorySize, SMEM);

    const int nblk = (NN + BM - 1) / BM;  // 782

    // degree (recomputed every call for determinism)
    fill_zero<<<64, 256>>>((float4*)deg, 2 * NN / 4);
    deg_kernel<<<(2 * NE + 255) / 256, 256>>>(ally_ei, enc_ei, deg);

    // input projection
    input_proj<<<NN / IPN, 128>>>(x, W_in, b_in, h);

    for (int i = 0; i < 2; i++) {
        const float* aW1 = ally_W1 + (size_t)i * 258 * H;
        const float* eW1 = enc_W1 + (size_t)i * 258 * H;

        // P/Q for both edge types; y==0 blocks additionally zero S
        gemm_kernel<0><<<dim3(nblk, 4), 128, SMEM>>>(
            h, H, H,
            aW1, aW1 + 128 * H, eW1, eW1 + 128 * H,
            ally_b1 + i * H, enc_b1 + i * H,
            nullptr, nullptr, nullptr, nullptr, nullptr, nullptr, nullptr,
            PQ, 4 * H, S);

        // edge scatter for both edge sets in one launch (2E warps)
        edge_kernel<<<2 * NE / 8, 256>>>(ally_ei, ally_ea, enc_ei, enc_ea,
                                         PQ, aW1 + 256 * H, eW1 + 256 * H, S);

        // combine: h = LN(h + S_a@W2a + dega*b2a + S_e@W2e + dege*b2e)
        gemm_kernel<1><<<nblk, 128, SMEM>>>(
            S, 2 * H, 2 * H,
            ally_W2 + (size_t)i * H * H, enc_W2 + (size_t)i * H * H,
            nullptr, nullptr, nullptr, nullptr,
            h, dega, dege,
            ally_b2 + i * H, enc_b2 + i * H,
            ln_g + i * H, ln_b + i * H,
            h, H, nullptr);

        // comb MLP: h = h + relu(h @ comb_W + comb_b); last layer writes d_out
        float* dst = (i == 1) ? out : h;
        gemm_kernel<2><<<nblk, 128, SMEM>>>(
            h, H, H,
            comb_W + (size_t)i * H * H, nullptr, nullptr, nullptr,
            comb_b + i * H, nullptr,
            h, nullptr, nullptr, nullptr, nullptr, nullptr, nullptr,
            dst, H, nullptr);
    }
}